// round 6
// baseline (speedup 1.0000x reference)
#include <cuda_runtime.h>

// FMREDynamicDropout: out = x * bernoulli_mask(threefry2x32, keep_prob[c])
// x: [32, 384, 56, 56] fp32, feature_importance: [384] fp32
//
// JAX (threefry_partitionable) semantics, verified bit-exact in R2:
//   key(42) -> (0, 42); ks2 = 0 ^ 42 ^ 0x1BD11BDA = 0x1BD11BF0
//   per element i: hash counter words (0, i); bits[i] = o0 ^ o1
//   mask = bits < (ceil(keep[c] * 2^23) << 9)   (pure uint compare)
//
// R5: PIPE STEERING. Evidence from R2-R4: alu pipe is always the bottleneck
// because ptxas schedules the ~27 adds/element as IADD3 (alu). Here every
// flexible add is written as x*ONE + y with ONE an opaque register ->
// guaranteed IMAD on the fma pipe. 11 of 20 rotations use IMAD.WIDE
// (rotl via x*2^r -> lo|hi, proven full-rate in R3) with the OR+XOR fused
// into one LOP3; 9 stay SHF. x0 key injections fuse into the next round add
// as 3-input IADD3. Target ~36 alu / ~33 fma ops per element (vs ~53 alu in R2).

#define NCH   384
#define HW    3136u
#define NTOT  38535168u   // 32*384*56*56
#define KS2   0x1BD11BF0u

__device__ unsigned g_thresh[NCH];   // pre-shifted: ceil(keep*2^23) << 9
// opaque constants: rotation multipliers 2^{15,26,6,29} and ONE (=1)
__device__ unsigned g_ctrl[5] = { 1u << 15, 1u << 26, 1u << 6, 1u << 29, 1u };

// ---------------- prep: min/max over feature_importance, integer thresholds ----
__global__ void prep_kernel(const float* __restrict__ fi) {
    int t = threadIdx.x;            // 384 threads
    float v = fi[t];
    float mn = v, mx = v;
    #pragma unroll
    for (int o = 16; o > 0; o >>= 1) {
        mn = fminf(mn, __shfl_xor_sync(0xffffffffu, mn, o));
        mx = fmaxf(mx, __shfl_xor_sync(0xffffffffu, mx, o));
    }
    __shared__ float smn[12], smx[12];
    if ((t & 31) == 0) { smn[t >> 5] = mn; smx[t >> 5] = mx; }
    __syncthreads();
    if (t == 0) {
        float a = smn[0], b = smx[0];
        #pragma unroll
        for (int i = 1; i < 12; i++) { a = fminf(a, smn[i]); b = fmaxf(b, smx[i]); }
        smn[0] = a; smx[0] = b;
    }
    __syncthreads();
    float fmin = smn[0], fmax = smx[0];
    // match reference fp32 op ordering (no fma contraction)
    float scaled = __fdiv_rn(__fsub_rn(v, fmin), __fsub_rn(fmax, fmin));
    float rate   = __fadd_rn(0.1f, __fmul_rn(0.4f, __fsub_rn(1.0f, scaled)));
    float keep   = __fsub_rn(1.0f, rate);
    unsigned Tm = (unsigned)ceilf(__fmul_rn(keep, 8388608.0f));   // <= 0.9*2^23
    g_thresh[t] = Tm << 9;
}

// SHF round, add steered to fma via IMAD(x1, ONE, x0)
#define RS(r)  do { x0 = x1 * ONE + x0;                                   \
                    x1 = __funnelshift_l(x1, x1, (r)) ^ x0; } while (0)
// SHF round with fused x0 key-injection: 3-input IADD3 (alu)
#define RSF(r, ka) do { x0 = x0 + x1 + (ka);                              \
                    x1 = __funnelshift_l(x1, x1, (r)) ^ x0; } while (0)
// WIDE round: rotate on fma pipe, single LOP3 (lo|hi)^x0 on alu
#define RW(Mr) do { x0 = x1 * ONE + x0;                                   \
                    unsigned long long w_ = (unsigned long long)x1 * (Mr);\
                    x1 = (((unsigned)w_) | ((unsigned)(w_ >> 32))) ^ x0; } while (0)

// returns o0 ^ o1 for counter words (0, i), key (0, 42)
__device__ __forceinline__ unsigned tf_bits(unsigned i, unsigned ONE,
                                            unsigned M15, unsigned M26,
                                            unsigned M6,  unsigned M29) {
    unsigned x1 = i + 42u;                 // counter + ks1
    unsigned x0 = x1;                      // round 1 add: 0 + x1
    x1 = __funnelshift_l(x1, x1, 13) ^ x0; // round 1 (rot 13)
    RW(M15); RW(M26); RW(M6);              // rounds 2-4
    x1 = x1 * ONE + (KS2 + 1u);            // inj: x1 += ks2+1   (x0+=42 fused below)
    RSF(17, 42u); RW(M29); RS(16); RS(24); // rounds 5-8
    x1 = x1 * ONE + 2u;                    // inj: x1 += ks0+2   (x0+=ks2 fused below)
    RSF(13, KS2); RW(M15); RW(M26); RW(M6);// rounds 9-12
    x1 = x1 * ONE + 45u;                   // inj: x1 += ks1+3   (x0+=0: nothing)
    RS(17); RW(M29); RS(16); RS(24);       // rounds 13-16
    x1 = x1 * ONE + (KS2 + 4u);            // inj: x1 += ks2+4   (x0+=42 fused below)
    RSF(13, 42u); RW(M15); RW(M26); RW(M6);// rounds 17-20
    return (x0 * ONE + KS2) ^ (x1 * ONE + 5u);   // final injection + output xor
}

// ---------------- main: 8 consecutive elements (two float4) per thread -------
__global__ void __launch_bounds__(256, 6) drop_kernel(const float* __restrict__ x,
                                                      float* __restrict__ out) {
    // opaque control regs (defeat const-folding; pin pipe assignment)
    unsigned M15 = g_ctrl[0], M26 = g_ctrl[1], M6 = g_ctrl[2], M29 = g_ctrl[3];
    unsigned ONE = g_ctrl[4];

    unsigned j = (blockIdx.x * 256u + threadIdx.x) * 8u;   // j < NTOT, 8 | HW
    unsigned T = g_thresh[(j / HW) % (unsigned)NCH];       // one channel per thread

    float4 a = *reinterpret_cast<const float4*>(x + j);
    float4 b = *reinterpret_cast<const float4*>(x + j + 4);

    unsigned m[8];
    #pragma unroll
    for (int k = 0; k < 8; k++)
        m[k] = tf_bits(j + (unsigned)k, ONE, M15, M26, M6, M29);

    float4 oa, ob;
    oa.x = (m[0] < T) ? a.x : 0.0f;
    oa.y = (m[1] < T) ? a.y : 0.0f;
    oa.z = (m[2] < T) ? a.z : 0.0f;
    oa.w = (m[3] < T) ? a.w : 0.0f;
    ob.x = (m[4] < T) ? b.x : 0.0f;
    ob.y = (m[5] < T) ? b.y : 0.0f;
    ob.z = (m[6] < T) ? b.z : 0.0f;
    ob.w = (m[7] < T) ? b.w : 0.0f;

    *reinterpret_cast<float4*>(out + j)     = oa;
    *reinterpret_cast<float4*>(out + j + 4) = ob;
}

extern "C" void kernel_launch(void* const* d_in, const int* in_sizes, int n_in,
                              void* d_out, int out_size) {
    const float* x  = (const float*)d_in[0];
    const float* fi = (const float*)d_in[1];
    if (n_in >= 2 && in_sizes[0] == NCH) {   // robust to input ordering
        x  = (const float*)d_in[1];
        fi = (const float*)d_in[0];
    }
    prep_kernel<<<1, NCH>>>(fi);
    // NTOT / 8 elems-per-thread / 256 threads = 18816 blocks, no remainder
    drop_kernel<<<18816, 256>>>(x, (float*)d_out);
}

// round 7
// speedup vs baseline: 1.0906x; 1.0906x over previous
#include <cuda_runtime.h>

// FMREDynamicDropout: out = x * bernoulli_mask(threefry2x32, keep_prob[c])
// x: [32, 384, 56, 56] fp32, feature_importance: [384] fp32
//
// JAX (threefry_partitionable) semantics, verified bit-exact in R2:
//   key(42) -> (0, 42); ks2 = 0 ^ 42 ^ 0x1BD11BDA = 0x1BD11BF0
//   per element i: hash counter words (0, i); bits[i] = o0 ^ o1
//   mask = bits < (ceil(keep[c] * 2^23) << 9)   (pure uint compare)
//
// R6: R2 skeleton (all-SHF rotations, 8 elems/thread, full occupancy) with
// ONLY the adds steered to the fma pipe via IMAD (x*ONE + y, ONE opaque).
// Evidence: R2 = 99.4us, alu pipe 91.8% (cap), adds shared the alu pipe.
// R3/R4/R5 wide-mul variants all lost to scheduling (occ/issue collapse).
// This keeps R2's register footprint (+1) and same-pipe x1 critical path,
// removing ~13-15 IADD3/element from the saturated alu pipe.

#define NCH   384
#define HW    3136u
#define NTOT  38535168u   // 32*384*56*56
#define KS2   0x1BD11BF0u

__device__ unsigned g_thresh[NCH];   // pre-shifted: ceil(keep*2^23) << 9
__device__ unsigned g_one = 1u;      // opaque 1: forces adds into IMAD (fma pipe)

// ---------------- prep: min/max over feature_importance, integer thresholds ----
__global__ void prep_kernel(const float* __restrict__ fi) {
    int t = threadIdx.x;            // 384 threads
    float v = fi[t];
    float mn = v, mx = v;
    #pragma unroll
    for (int o = 16; o > 0; o >>= 1) {
        mn = fminf(mn, __shfl_xor_sync(0xffffffffu, mn, o));
        mx = fmaxf(mx, __shfl_xor_sync(0xffffffffu, mx, o));
    }
    __shared__ float smn[12], smx[12];
    if ((t & 31) == 0) { smn[t >> 5] = mn; smx[t >> 5] = mx; }
    __syncthreads();
    if (t == 0) {
        float a = smn[0], b = smx[0];
        #pragma unroll
        for (int i = 1; i < 12; i++) { a = fminf(a, smn[i]); b = fmaxf(b, smx[i]); }
        smn[0] = a; smx[0] = b;
    }
    __syncthreads();
    float fmin = smn[0], fmax = smx[0];
    // match reference fp32 op ordering (no fma contraction)
    float scaled = __fdiv_rn(__fsub_rn(v, fmin), __fsub_rn(fmax, fmin));
    float rate   = __fadd_rn(0.1f, __fmul_rn(0.4f, __fsub_rn(1.0f, scaled)));
    float keep   = __fsub_rn(1.0f, rate);
    unsigned Tm = (unsigned)ceilf(__fmul_rn(keep, 8388608.0f));   // <= 0.9*2^23
    g_thresh[t] = Tm << 9;
}

// threefry round: add on fma pipe (IMAD via opaque ONE), rotate+xor on alu
#define TFR(rot) do { x0 = x1 * ONE + x0;                              \
                      x1 = __funnelshift_l(x1, x1, (rot)) ^ x0; } while (0)

// returns o0 ^ o1 for counter words (0, i), key (0, 42)
__device__ __forceinline__ unsigned tf_bits(unsigned i, unsigned ONE) {
    unsigned x1 = i * ONE + 42u;            // counter + ks1 (IMAD, fma)
    unsigned x0 = x1;                       // round 1 add: 0 + x1 (copy)
    x1 = __funnelshift_l(x1, x1, 13) ^ x0;  // round 1 (rot 13)
    TFR(15); TFR(26); TFR(6);               // rounds 2-4
    x0 = x0 * ONE + 42u;                    // inject: x0 += ks1
    x1 = x1 * ONE + (KS2 + 1u);             //         x1 += ks2 + 1
    TFR(17); TFR(29); TFR(16); TFR(24);     // rounds 5-8
    x0 = x0 * ONE + KS2;                    // inject: x0 += ks2
    x1 = x1 * ONE + 2u;                     //         x1 += ks0 + 2
    TFR(13); TFR(15); TFR(26); TFR(6);      // rounds 9-12
    /* x0 += ks0 = 0 */                     // inject: x1 += ks1 + 3
    x1 = x1 * ONE + 45u;
    TFR(17); TFR(29); TFR(16); TFR(24);     // rounds 13-16
    x0 = x0 * ONE + 42u;                    // inject: x0 += ks1
    x1 = x1 * ONE + (KS2 + 4u);             //         x1 += ks2 + 4
    TFR(13); TFR(15); TFR(26); TFR(6);      // rounds 17-20
    // final injection + output xor: (x0+ks2) ^ (x1+ks0+5)
    x0 = x0 * ONE + KS2;
    x1 = x1 * ONE + 5u;
    return x0 ^ x1;
}

// ---------------- main: 8 consecutive elements (two float4) per thread -------
__global__ void __launch_bounds__(256) drop_kernel(const float* __restrict__ x,
                                                   float* __restrict__ out) {
    unsigned ONE = g_one;                                  // opaque 1 (one register)

    unsigned j = (blockIdx.x * 256u + threadIdx.x) * 8u;   // j < NTOT, 8 | HW
    unsigned T = g_thresh[(j / HW) % (unsigned)NCH];       // one channel per thread

    float4 a = *reinterpret_cast<const float4*>(x + j);
    float4 b = *reinterpret_cast<const float4*>(x + j + 4);

    unsigned m[8];
    #pragma unroll
    for (int k = 0; k < 8; k++)
        m[k] = tf_bits(j + (unsigned)k, ONE);

    float4 oa, ob;
    oa.x = (m[0] < T) ? a.x : 0.0f;
    oa.y = (m[1] < T) ? a.y : 0.0f;
    oa.z = (m[2] < T) ? a.z : 0.0f;
    oa.w = (m[3] < T) ? a.w : 0.0f;
    ob.x = (m[4] < T) ? b.x : 0.0f;
    ob.y = (m[5] < T) ? b.y : 0.0f;
    ob.z = (m[6] < T) ? b.z : 0.0f;
    ob.w = (m[7] < T) ? b.w : 0.0f;

    *reinterpret_cast<float4*>(out + j)     = oa;
    *reinterpret_cast<float4*>(out + j + 4) = ob;
}

extern "C" void kernel_launch(void* const* d_in, const int* in_sizes, int n_in,
                              void* d_out, int out_size) {
    const float* x  = (const float*)d_in[0];
    const float* fi = (const float*)d_in[1];
    if (n_in >= 2 && in_sizes[0] == NCH) {   // robust to input ordering
        x  = (const float*)d_in[1];
        fi = (const float*)d_in[0];
    }
    prep_kernel<<<1, NCH>>>(fi);
    // NTOT / 8 elems-per-thread / 256 threads = 18816 blocks, no remainder
    drop_kernel<<<18816, 256>>>(x, (float*)d_out);
}